// round 15
// baseline (speedup 1.0000x reference)
#include <cuda_runtime.h>

// ---------------- problem constants ----------------
#define TBS   128          // T*B = 4*32
#define SEQ   81           // 9*9
#define CH    128          // width C
#define MROWS (TBS*SEQ)    // 10368 rows
#define NQKV  384          // 3*C
#define EPSLN 1e-5f

typedef unsigned long long ull;

// ---------------- scratch (static device globals; no allocation) ------------
__device__ float  g_h  [MROWS*CH];    // residual stream
__device__ float2 g_stats[MROWS];     // per-row (mu, rstd) of g_h
__device__ float  g_qkv[MROWS*NQKV];  // qkv projection

// ---------------- packed f32x2 helpers --------------------------------------
__device__ __forceinline__ ull pk2(float x, float y) {
    ull r;
    asm("mov.b64 %0, {%1, %2};"
        : "=l"(r) : "r"(__float_as_uint(x)), "r"(__float_as_uint(y)));
    return r;
}
__device__ __forceinline__ ull fma2(ull a, ull b, ull c) {
    ull d;
    asm("fma.rn.f32x2 %0, %1, %2, %3;" : "=l"(d) : "l"(a), "l"(b), "l"(c));
    return d;
}
__device__ __forceinline__ void upk2(ull v, float& x, float& y) {
    unsigned int lo, hi;
    asm("mov.b64 {%0, %1}, %2;" : "=r"(lo), "=r"(hi) : "l"(v));
    x = __uint_as_float(lo);
    y = __uint_as_float(hi);
}
__device__ __forceinline__ float ex2(float x) {
    float r;
    asm("ex2.approx.f32 %0, %1;" : "=f"(r) : "f"(x));
    return r;
}

// ---------------- input projection + LN stats --------------------------------
__global__ void __launch_bounds__(256) inproj_kernel(const float* __restrict__ x,
                                                     const float* __restrict__ in_w,
                                                     const float* __restrict__ in_b) {
    int row  = blockIdx.x * 8 + (threadIdx.x >> 5);
    int lane = threadIdx.x & 31;
    float x0 = __ldg(&x[row * 2]);
    float x1 = __ldg(&x[row * 2 + 1]);
    float s = 0.f, ss = 0.f;
    float* hr = g_h + (size_t)row * CH;
#pragma unroll
    for (int j = 0; j < 4; j++) {
        int c = lane + 32 * j;
        float h = fmaf(x0, in_w[c], fmaf(x1, in_w[CH + c], in_b[c]));
        hr[c] = h;
        s += h;
        ss = fmaf(h, h, ss);
    }
#pragma unroll
    for (int o = 16; o; o >>= 1) {
        s  += __shfl_xor_sync(0xffffffffu, s, o);
        ss += __shfl_xor_sync(0xffffffffu, ss, o);
    }
    if (lane == 0) {
        float mu  = s * (1.0f / CH);
        float var = fmaf(-mu, mu, ss * (1.0f / CH));
        g_stats[row] = make_float2(mu, rsqrtf(var + EPSLN));
    }
}

// ---------------- fused LN + QKV GEMM (R7-measured: 128x128, double-buffered) -
__global__ void __launch_bounds__(256) qkv_gemm(const float* __restrict__ W,
                                                const float* __restrict__ bias,
                                                const float* __restrict__ gam,
                                                const float* __restrict__ bet) {
    __shared__ float gsh[CH], bsh[CH];
    __shared__ __align__(16) float As[2][16][128];
    __shared__ __align__(16) float Bs[2][16][128];

    int tid = threadIdx.x;
    if (tid < 128) { gsh[tid] = gam[tid]; bsh[tid] = bet[tid]; }

    int tx = tid & 15;              // output cols 8*tx .. +7
    int ty = tid >> 4;              // output rows 8*ty .. +7

    int arow = tid & 127;           // A staging: row
    int akh  = (tid >> 7) << 3;     // A staging: k half (0 or 8)
    int brow = tid >> 4;            // B staging: k row 0..15
    int bcol = (tid & 15) << 3;     // B staging: col

    size_t mBase = (size_t)blockIdx.y * 128;
    int    nBase = blockIdx.x * 128;
    const float* hp = g_h + (mBase + arow) * CH + akh;
    float2 st = g_stats[mBase + arow];
    float c1 = st.y;                // rstd
    float c0 = -st.x * st.y;        // -mu*rstd
    const float* Bp = W + (size_t)brow * NQKV + nBase + bcol;

    ull acc[8][4];
#pragma unroll
    for (int m = 0; m < 8; m++)
#pragma unroll
        for (int j = 0; j < 4; j++) acc[m][j] = 0ull;

    // prologue: fetch chunk 0
    float4 pa0 = *(const float4*)(hp);
    float4 pa1 = *(const float4*)(hp + 4);
    float4 pb0 = *(const float4*)(Bp);
    float4 pb1 = *(const float4*)(Bp + 4);
    __syncthreads();                // gsh/bsh visible
    {
        float av[8] = {pa0.x, pa0.y, pa0.z, pa0.w, pa1.x, pa1.y, pa1.z, pa1.w};
#pragma unroll
        for (int j = 0; j < 8; j++) {
            int kk = akh + j;
            As[0][kk][arow] = fmaf(fmaf(av[j], c1, c0), gsh[kk], bsh[kk]);
        }
        *(float4*)&Bs[0][brow][bcol]     = pb0;
        *(float4*)&Bs[0][brow][bcol + 4] = pb1;
    }
    __syncthreads();

#pragma unroll
    for (int i = 0; i < 8; i++) {
        int buf = i & 1;
        if (i < 7) {                // prefetch next chunk into regs
            const float* hq = hp + (i + 1) * 16;
            const float* bq = Bp + (size_t)(i + 1) * 16 * NQKV;
            pa0 = *(const float4*)(hq);
            pa1 = *(const float4*)(hq + 4);
            pb0 = *(const float4*)(bq);
            pb1 = *(const float4*)(bq + 4);
        }
#pragma unroll
        for (int k = 0; k < 16; k++) {
            float4 aA = *(const float4*)&As[buf][k][8 * ty];
            float4 aB = *(const float4*)&As[buf][k][8 * ty + 4];
            ulonglong2 q0 = *(const ulonglong2*)&Bs[buf][k][8 * tx];
            ulonglong2 q1 = *(const ulonglong2*)&Bs[buf][k][8 * tx + 4];
            ull bp2[4] = {q0.x, q0.y, q1.x, q1.y};
            float am[8] = {aA.x, aA.y, aA.z, aA.w, aB.x, aB.y, aB.z, aB.w};
#pragma unroll
            for (int m = 0; m < 8; m++) {
                ull aa = pk2(am[m], am[m]);
#pragma unroll
                for (int j = 0; j < 4; j++)
                    acc[m][j] = fma2(aa, bp2[j], acc[m][j]);
            }
        }
        if (i < 7) {                // stage next chunk into other buffer
            int nb = buf ^ 1;
            int k0 = (i + 1) * 16;
            float av[8] = {pa0.x, pa0.y, pa0.z, pa0.w, pa1.x, pa1.y, pa1.z, pa1.w};
#pragma unroll
            for (int j = 0; j < 8; j++) {
                int kk = akh + j;
                As[nb][kk][arow] = fmaf(fmaf(av[j], c1, c0), gsh[k0 + kk], bsh[k0 + kk]);
            }
            *(float4*)&Bs[nb][brow][bcol]     = pb0;
            *(float4*)&Bs[nb][brow][bcol + 4] = pb1;
            __syncthreads();
        }
    }

    int colBase = nBase + 8 * tx;
    float bb[8];
    *(float4*)(bb)     = *(const float4*)(bias + colBase);
    *(float4*)(bb + 4) = *(const float4*)(bias + colBase + 4);
#pragma unroll
    for (int m = 0; m < 8; m++) {
        size_t row = mBase + 8 * ty + m;
        float v[8];
#pragma unroll
        for (int j = 0; j < 4; j++) upk2(acc[m][j], v[2 * j], v[2 * j + 1]);
#pragma unroll
        for (int j = 0; j < 8; j++) v[j] += bb[j];
        float* o = g_qkv + row * NQKV + colBase;
        *(float4*)(o)     = make_float4(v[0], v[1], v[2], v[3]);
        *(float4*)(o + 4) = make_float4(v[4], v[5], v[6], v[7]);
    }
}

// ---------------- fused attention + FFN + residual + LN stats (R13 WIN) ------
#define QT 9
#define KT 27
__global__ void __launch_bounds__(128, 8) attn_ffn_kernel(const float* __restrict__ W,
                                                          const float* __restrict__ bias) {
    int b  = blockIdx.y;
    int q0 = blockIdx.x * QT;
    int c  = threadIdx.x;

    __shared__ float ks[KT][CH];
    __shared__ float vs[KT][CH];

    const float* base = g_qkv + (size_t)b * SEQ * NQKV;
    const float LOG2E = 1.4426950408889634f;

    float qv[QT], num[QT], den[QT];
#pragma unroll
    for (int i = 0; i < QT; i++) {
        qv[i]  = base[(size_t)(q0 + i) * NQKV + c] * LOG2E;
        num[i] = 0.f;
        den[i] = 0.f;
    }

#pragma unroll 1
    for (int kc = 0; kc < SEQ; kc += KT) {
        __syncthreads();
#pragma unroll
        for (int r = 0; r < KT; r++) {
            ks[r][c] = base[(size_t)(kc + r) * NQKV + CH     + c];
            vs[r][c] = base[(size_t)(kc + r) * NQKV + 2 * CH + c];
        }
        __syncthreads();
#pragma unroll 3
        for (int r = 0; r < KT; r++) {
            float kk = ks[r][c];
            float vv = vs[r][c];
#pragma unroll
            for (int i = 0; i < QT; i++) {
                float e = ex2(qv[i] * kk);
                num[i] = fmaf(e, vv, num[i]);
                den[i] += e;
            }
        }
    }

    // ---- stage att rows in smem (reuse ks; all warps done reading it) ------
    __syncthreads();
    float (*att_s)[CH] = ks;
#pragma unroll
    for (int i = 0; i < QT; i++) att_s[i][c] = __fdividef(num[i], den[i]);
    __syncthreads();

    // ---- FFN: y[i] = sum_k att[i][k] * W[k][c]  (idle FMA pipe) ------------
    float y[QT];
#pragma unroll
    for (int i = 0; i < QT; i++) y[i] = 0.f;
#pragma unroll 2
    for (int k = 0; k < CH; k += 4) {
        float w0 = W[(size_t)(k + 0) * CH + c];
        float w1 = W[(size_t)(k + 1) * CH + c];
        float w2 = W[(size_t)(k + 2) * CH + c];
        float w3 = W[(size_t)(k + 3) * CH + c];
#pragma unroll
        for (int i = 0; i < QT; i++) {
            float4 a = *(const float4*)&att_s[i][k];   // LDS.128 broadcast
            y[i] = fmaf(a.x, w0, y[i]);
            y[i] = fmaf(a.y, w1, y[i]);
            y[i] = fmaf(a.z, w2, y[i]);
            y[i] = fmaf(a.w, w3, y[i]);
        }
    }

    // ---- bias + relu + residual + write h; collect per-row stats -----------
    float bb = bias[c];
    size_t rowBase = (size_t)b * SEQ + q0;
    int wid  = c >> 5;
    int lane = c & 31;
    float* rs  = (float*)vs;           // [4][QT] partial sums (vs is dead)
    float* rss = rs + 4 * QT;          // [4][QT] partial sumsq

    float hn[QT];
#pragma unroll
    for (int i = 0; i < QT; i++) {
        float v = fmaxf(y[i] + bb, 0.f);
        float* hp = g_h + (rowBase + i) * CH + c;
        float h = *hp + v;
        *hp = h;
        hn[i] = h;
    }
#pragma unroll
    for (int i = 0; i < QT; i++) {
        float s  = hn[i];
        float ss = hn[i] * hn[i];
#pragma unroll
        for (int o = 16; o; o >>= 1) {
            s  += __shfl_xor_sync(0xffffffffu, s, o);
            ss += __shfl_xor_sync(0xffffffffu, ss, o);
        }
        if (lane == 0) { rs[wid * QT + i] = s; rss[wid * QT + i] = ss; }
    }
    __syncthreads();
    if (c < QT) {
        float s  = rs[c]  + rs[QT + c]  + rs[2 * QT + c]  + rs[3 * QT + c];
        float ss = rss[c] + rss[QT + c] + rss[2 * QT + c] + rss[3 * QT + c];
        float mu  = s * (1.0f / CH);
        float var = fmaf(-mu, mu, ss * (1.0f / CH));
        g_stats[rowBase + c] = make_float2(mu, rsqrtf(var + EPSLN));
    }
}

// ---------------- final projection: out = h @ out_w + out_b ------------------
__global__ void __launch_bounds__(256) outproj_kernel(const float* __restrict__ ow,
                                                      const float* __restrict__ ob,
                                                      float* __restrict__ out) {
    int row  = blockIdx.x * 8 + (threadIdx.x >> 5);
    int lane = threadIdx.x & 31;
    const float* hr = g_h + (size_t)row * CH;
    float a0 = 0.f, a1 = 0.f, a2 = 0.f, a3 = 0.f;
#pragma unroll
    for (int j = 0; j < 4; j++) {
        int cidx = lane + 32 * j;
        float hv = hr[cidx];
        const float* w = ow + cidx * 4;
        a0 = fmaf(hv, w[0], a0);
        a1 = fmaf(hv, w[1], a1);
        a2 = fmaf(hv, w[2], a2);
        a3 = fmaf(hv, w[3], a3);
    }
#pragma unroll
    for (int o = 16; o; o >>= 1) {
        a0 += __shfl_xor_sync(0xffffffffu, a0, o);
        a1 += __shfl_xor_sync(0xffffffffu, a1, o);
        a2 += __shfl_xor_sync(0xffffffffu, a2, o);
        a3 += __shfl_xor_sync(0xffffffffu, a3, o);
    }
    if (lane == 0) {
        *(float4*)(out + (size_t)row * 4) =
            make_float4(a0 + ob[0], a1 + ob[1], a2 + ob[2], a3 + ob[3]);
    }
}

// ---------------- launch -----------------------------------------------------
extern "C" void kernel_launch(void* const* d_in, const int* in_sizes, int n_in,
                              void* d_out, int out_size) {
    const float* x      = (const float*)d_in[0];
    const float* in_w   = (const float*)d_in[1];
    const float* in_b   = (const float*)d_in[2];
    const float* ln_g   = (const float*)d_in[3];
    const float* ln_b   = (const float*)d_in[4];
    const float* qkv_w  = (const float*)d_in[5];
    const float* qkv_b  = (const float*)d_in[6];
    const float* full_w = (const float*)d_in[7];
    const float* full_b = (const float*)d_in[8];
    const float* out_w  = (const float*)d_in[9];
    const float* out_b  = (const float*)d_in[10];
    float* out = (float*)d_out;

    inproj_kernel<<<MROWS / 8, 256>>>(x, in_w, in_b);

    for (int l = 0; l < 4; l++) {
        qkv_gemm<<<dim3(NQKV / 128, MROWS / 128), 256>>>(
            qkv_w + (size_t)l * CH * NQKV, qkv_b + l * NQKV,
            ln_g + l * CH, ln_b + l * CH);
        attn_ffn_kernel<<<dim3(SEQ / QT, TBS), 128>>>(
            full_w + (size_t)l * CH * CH, full_b + l * CH);
    }

    outproj_kernel<<<MROWS / 8, 256>>>(out_w, out_b, out);
}

// round 16
// speedup vs baseline: 1.6921x; 1.6921x over previous
#include <cuda_runtime.h>

// ---------------- problem constants ----------------
#define TBS   128          // T*B = 4*32
#define SEQ   81           // 9*9
#define CH    128          // width C
#define MROWS (TBS*SEQ)    // 10368 rows
#define NQKV  384          // 3*C
#define EPSLN 1e-5f

typedef unsigned long long ull;

// ---------------- scratch (static device globals; no allocation) ------------
__device__ float  g_h  [MROWS*CH];    // residual stream
__device__ float2 g_stats[MROWS];     // per-row (mu, rstd) of g_h
__device__ float  g_qkv[MROWS*NQKV];  // qkv projection

// ---------------- packed f32x2 helpers --------------------------------------
__device__ __forceinline__ ull pk2(float x, float y) {
    ull r;
    asm("mov.b64 %0, {%1, %2};"
        : "=l"(r) : "r"(__float_as_uint(x)), "r"(__float_as_uint(y)));
    return r;
}
__device__ __forceinline__ ull fma2(ull a, ull b, ull c) {
    ull d;
    asm("fma.rn.f32x2 %0, %1, %2, %3;" : "=l"(d) : "l"(a), "l"(b), "l"(c));
    return d;
}
__device__ __forceinline__ void upk2(ull v, float& x, float& y) {
    unsigned int lo, hi;
    asm("mov.b64 {%0, %1}, %2;" : "=r"(lo), "=r"(hi) : "l"(v));
    x = __uint_as_float(lo);
    y = __uint_as_float(hi);
}
__device__ __forceinline__ float ex2(float x) {
    float r;
    asm("ex2.approx.f32 %0, %1;" : "=f"(r) : "f"(x));
    return r;
}

// ---------------- input projection + LN stats --------------------------------
__global__ void __launch_bounds__(256) inproj_kernel(const float* __restrict__ x,
                                                     const float* __restrict__ in_w,
                                                     const float* __restrict__ in_b) {
    int row  = blockIdx.x * 8 + (threadIdx.x >> 5);
    int lane = threadIdx.x & 31;
    float x0 = __ldg(&x[row * 2]);
    float x1 = __ldg(&x[row * 2 + 1]);
    float s = 0.f, ss = 0.f;
    float* hr = g_h + (size_t)row * CH;
#pragma unroll
    for (int j = 0; j < 4; j++) {
        int c = lane + 32 * j;
        float h = fmaf(x0, in_w[c], fmaf(x1, in_w[CH + c], in_b[c]));
        hr[c] = h;
        s += h;
        ss = fmaf(h, h, ss);
    }
#pragma unroll
    for (int o = 16; o; o >>= 1) {
        s  += __shfl_xor_sync(0xffffffffu, s, o);
        ss += __shfl_xor_sync(0xffffffffu, ss, o);
    }
    if (lane == 0) {
        float mu  = s * (1.0f / CH);
        float var = fmaf(-mu, mu, ss * (1.0f / CH));
        g_stats[row] = make_float2(mu, rsqrtf(var + EPSLN));
    }
}

// ---------------- fused LN + QKV GEMM ----------------------------------------
// R14's 64x64 tile and inner loop; double-buffered smem + register prefetch
// (R7-validated one-sync-per-chunk protocol) to hide inter-chunk L2 latency.
__global__ void __launch_bounds__(256) qkv_gemm(const float* __restrict__ W,
                                                const float* __restrict__ bias,
                                                const float* __restrict__ gam,
                                                const float* __restrict__ bet) {
    __shared__ float gsh[CH], bsh[CH];
    __shared__ __align__(16) float As[2][16][64];
    __shared__ __align__(16) float Bs[2][16][64];

    int tid = threadIdx.x;
    if (tid < 128) { gsh[tid] = gam[tid]; bsh[tid] = bet[tid]; }

    int tx  = tid & 15;
    int ty  = tid >> 4;

    ull acc[4][2];
#pragma unroll
    for (int m = 0; m < 4; m++) { acc[m][0] = 0ull; acc[m][1] = 0ull; }

    int ar = tid >> 2;             // A staging row 0..63
    int ac = (tid & 3) << 2;       // A staging k offset 0,4,8,12
    int br = tid >> 4;             // B staging k row 0..15
    int bc = (tid & 15) << 2;      // B staging col

    size_t mBase = (size_t)blockIdx.y * 64;
    const float* Aload = g_h + (mBase + ar) * CH + ac;
    const float* Bload = W + (size_t)br * NQKV + blockIdx.x * 64 + bc;
    float2 st = g_stats[mBase + ar];
    float c1 = st.y;               // rstd
    float c0 = -st.x * st.y;       // -mu*rstd

    // prologue: fetch + stage chunk 0
    float4 pa = *(const float4*)(Aload);
    float4 pb = *(const float4*)(Bload);
    __syncthreads();               // gsh/bsh visible
    As[0][ac + 0][ar] = fmaf(fmaf(pa.x, c1, c0), gsh[ac + 0], bsh[ac + 0]);
    As[0][ac + 1][ar] = fmaf(fmaf(pa.y, c1, c0), gsh[ac + 1], bsh[ac + 1]);
    As[0][ac + 2][ar] = fmaf(fmaf(pa.z, c1, c0), gsh[ac + 2], bsh[ac + 2]);
    As[0][ac + 3][ar] = fmaf(fmaf(pa.w, c1, c0), gsh[ac + 3], bsh[ac + 3]);
    *(float4*)&Bs[0][br][bc] = pb;
    __syncthreads();

#pragma unroll
    for (int i = 0; i < 8; i++) {
        int buf = i & 1;
        if (i < 7) {               // prefetch chunk i+1 into regs
            pa = *(const float4*)(Aload + (i + 1) * 16);
            pb = *(const float4*)(Bload + (size_t)(i + 1) * 16 * NQKV);
        }
#pragma unroll
        for (int k = 0; k < 16; k++) {
            float4 a4 = *(const float4*)&As[buf][k][ty << 2];   // LDS.128 broadcast
            float4 b4 = *(const float4*)&Bs[buf][k][tx << 2];
            ull b01 = pk2(b4.x, b4.y);
            ull b23 = pk2(b4.z, b4.w);
            ull a0 = pk2(a4.x, a4.x);
            ull a1 = pk2(a4.y, a4.y);
            ull a2 = pk2(a4.z, a4.z);
            ull a3 = pk2(a4.w, a4.w);
            acc[0][0] = fma2(a0, b01, acc[0][0]);
            acc[0][1] = fma2(a0, b23, acc[0][1]);
            acc[1][0] = fma2(a1, b01, acc[1][0]);
            acc[1][1] = fma2(a1, b23, acc[1][1]);
            acc[2][0] = fma2(a2, b01, acc[2][0]);
            acc[2][1] = fma2(a2, b23, acc[2][1]);
            acc[3][0] = fma2(a3, b01, acc[3][0]);
            acc[3][1] = fma2(a3, b23, acc[3][1]);
        }
        if (i < 7) {               // stage chunk i+1 into the other buffer
            int nb = buf ^ 1;
            int k0 = (i + 1) * 16;
            As[nb][ac + 0][ar] = fmaf(fmaf(pa.x, c1, c0), gsh[k0 + ac + 0], bsh[k0 + ac + 0]);
            As[nb][ac + 1][ar] = fmaf(fmaf(pa.y, c1, c0), gsh[k0 + ac + 1], bsh[k0 + ac + 1]);
            As[nb][ac + 2][ar] = fmaf(fmaf(pa.z, c1, c0), gsh[k0 + ac + 2], bsh[k0 + ac + 2]);
            As[nb][ac + 3][ar] = fmaf(fmaf(pa.w, c1, c0), gsh[k0 + ac + 3], bsh[k0 + ac + 3]);
            *(float4*)&Bs[nb][br][bc] = pb;
            __syncthreads();
        }
    }

    int col = blockIdx.x * 64 + (tx << 2);
    float4 bi = *(const float4*)(bias + col);
#pragma unroll
    for (int m = 0; m < 4; m++) {
        size_t row = mBase + (ty << 2) + m;
        float r0, r1, r2, r3;
        upk2(acc[m][0], r0, r1);
        upk2(acc[m][1], r2, r3);
        *(float4*)(g_qkv + row * NQKV + col) =
            make_float4(r0 + bi.x, r1 + bi.y, r2 + bi.z, r3 + bi.w);
    }
}

// ---------------- fused attention + FFN + residual + LN stats (R13/R14 WIN) --
#define QT 9
#define KT 27
__global__ void __launch_bounds__(128, 8) attn_ffn_kernel(const float* __restrict__ W,
                                                          const float* __restrict__ bias) {
    int b  = blockIdx.y;
    int q0 = blockIdx.x * QT;
    int c  = threadIdx.x;

    __shared__ float ks[KT][CH];
    __shared__ float vs[KT][CH];

    const float* base = g_qkv + (size_t)b * SEQ * NQKV;
    const float LOG2E = 1.4426950408889634f;

    float qv[QT], num[QT], den[QT];
#pragma unroll
    for (int i = 0; i < QT; i++) {
        qv[i]  = base[(size_t)(q0 + i) * NQKV + c] * LOG2E;
        num[i] = 0.f;
        den[i] = 0.f;
    }

#pragma unroll 1
    for (int kc = 0; kc < SEQ; kc += KT) {
        __syncthreads();
#pragma unroll
        for (int r = 0; r < KT; r++) {
            ks[r][c] = base[(size_t)(kc + r) * NQKV + CH     + c];
            vs[r][c] = base[(size_t)(kc + r) * NQKV + 2 * CH + c];
        }
        __syncthreads();
#pragma unroll 3
        for (int r = 0; r < KT; r++) {
            float kk = ks[r][c];
            float vv = vs[r][c];
#pragma unroll
            for (int i = 0; i < QT; i++) {
                float e = ex2(qv[i] * kk);
                num[i] = fmaf(e, vv, num[i]);
                den[i] += e;
            }
        }
    }

    // ---- stage att rows in smem (reuse ks; all warps done reading it) ------
    __syncthreads();
    float (*att_s)[CH] = ks;
#pragma unroll
    for (int i = 0; i < QT; i++) att_s[i][c] = __fdividef(num[i], den[i]);
    __syncthreads();

    // ---- FFN: y[i] = sum_k att[i][k] * W[k][c]  (idle FMA pipe) ------------
    float y[QT];
#pragma unroll
    for (int i = 0; i < QT; i++) y[i] = 0.f;
#pragma unroll 2
    for (int k = 0; k < CH; k += 4) {
        float w0 = W[(size_t)(k + 0) * CH + c];
        float w1 = W[(size_t)(k + 1) * CH + c];
        float w2 = W[(size_t)(k + 2) * CH + c];
        float w3 = W[(size_t)(k + 3) * CH + c];
#pragma unroll
        for (int i = 0; i < QT; i++) {
            float4 a = *(const float4*)&att_s[i][k];   // LDS.128 broadcast
            y[i] = fmaf(a.x, w0, y[i]);
            y[i] = fmaf(a.y, w1, y[i]);
            y[i] = fmaf(a.z, w2, y[i]);
            y[i] = fmaf(a.w, w3, y[i]);
        }
    }

    // ---- bias + relu + residual + write h; collect per-row stats -----------
    float bb = bias[c];
    size_t rowBase = (size_t)b * SEQ + q0;
    int wid  = c >> 5;
    int lane = c & 31;
    float* rs  = (float*)vs;           // [4][QT] partial sums (vs is dead)
    float* rss = rs + 4 * QT;          // [4][QT] partial sumsq

    float hn[QT];
#pragma unroll
    for (int i = 0; i < QT; i++) {
        float v = fmaxf(y[i] + bb, 0.f);
        float* hp = g_h + (rowBase + i) * CH + c;
        float h = *hp + v;
        *hp = h;
        hn[i] = h;
    }
#pragma unroll
    for (int i = 0; i < QT; i++) {
        float s  = hn[i];
        float ss = hn[i] * hn[i];
#pragma unroll
        for (int o = 16; o; o >>= 1) {
            s  += __shfl_xor_sync(0xffffffffu, s, o);
            ss += __shfl_xor_sync(0xffffffffu, ss, o);
        }
        if (lane == 0) { rs[wid * QT + i] = s; rss[wid * QT + i] = ss; }
    }
    __syncthreads();
    if (c < QT) {
        float s  = rs[c]  + rs[QT + c]  + rs[2 * QT + c]  + rs[3 * QT + c];
        float ss = rss[c] + rss[QT + c] + rss[2 * QT + c] + rss[3 * QT + c];
        float mu  = s * (1.0f / CH);
        float var = fmaf(-mu, mu, ss * (1.0f / CH));
        g_stats[rowBase + c] = make_float2(mu, rsqrtf(var + EPSLN));
    }
}

// ---------------- final projection: out = h @ out_w + out_b ------------------
__global__ void __launch_bounds__(256) outproj_kernel(const float* __restrict__ ow,
                                                      const float* __restrict__ ob,
                                                      float* __restrict__ out) {
    int row  = blockIdx.x * 8 + (threadIdx.x >> 5);
    int lane = threadIdx.x & 31;
    const float* hr = g_h + (size_t)row * CH;
    float a0 = 0.f, a1 = 0.f, a2 = 0.f, a3 = 0.f;
#pragma unroll
    for (int j = 0; j < 4; j++) {
        int cidx = lane + 32 * j;
        float hv = hr[cidx];
        const float* w = ow + cidx * 4;
        a0 = fmaf(hv, w[0], a0);
        a1 = fmaf(hv, w[1], a1);
        a2 = fmaf(hv, w[2], a2);
        a3 = fmaf(hv, w[3], a3);
    }
#pragma unroll
    for (int o = 16; o; o >>= 1) {
        a0 += __shfl_xor_sync(0xffffffffu, a0, o);
        a1 += __shfl_xor_sync(0xffffffffu, a1, o);
        a2 += __shfl_xor_sync(0xffffffffu, a2, o);
        a3 += __shfl_xor_sync(0xffffffffu, a3, o);
    }
    if (lane == 0) {
        *(float4*)(out + (size_t)row * 4) =
            make_float4(a0 + ob[0], a1 + ob[1], a2 + ob[2], a3 + ob[3]);
    }
}

// ---------------- launch -----------------------------------------------------
extern "C" void kernel_launch(void* const* d_in, const int* in_sizes, int n_in,
                              void* d_out, int out_size) {
    const float* x      = (const float*)d_in[0];
    const float* in_w   = (const float*)d_in[1];
    const float* in_b   = (const float*)d_in[2];
    const float* ln_g   = (const float*)d_in[3];
    const float* ln_b   = (const float*)d_in[4];
    const float* qkv_w  = (const float*)d_in[5];
    const float* qkv_b  = (const float*)d_in[6];
    const float* full_w = (const float*)d_in[7];
    const float* full_b = (const float*)d_in[8];
    const float* out_w  = (const float*)d_in[9];
    const float* out_b  = (const float*)d_in[10];
    float* out = (float*)d_out;

    inproj_kernel<<<MROWS / 8, 256>>>(x, in_w, in_b);

    for (int l = 0; l < 4; l++) {
        qkv_gemm<<<dim3(NQKV / 64, MROWS / 64), 256>>>(
            qkv_w + (size_t)l * CH * NQKV, qkv_b + l * NQKV,
            ln_g + l * CH, ln_b + l * CH);
        attn_ffn_kernel<<<dim3(SEQ / QT, TBS), 128>>>(
            full_w + (size_t)l * CH * CH, full_b + l * CH);
    }

    outproj_kernel<<<MROWS / 8, 256>>>(out_w, out_b, out);
}

// round 17
// speedup vs baseline: 1.7395x; 1.0280x over previous
#include <cuda_runtime.h>

// ---------------- problem constants ----------------
#define TBS   128          // T*B = 4*32
#define SEQ   81           // 9*9
#define CH    128          // width C
#define MROWS (TBS*SEQ)    // 10368 rows
#define NQKV  384          // 3*C
#define NLAY  4
#define EPSLN 1e-5f

typedef unsigned long long ull;

// ---------------- scratch (static device globals; no allocation) ------------
__device__ float  g_h  [MROWS*CH];      // residual stream
__device__ float2 g_stats[MROWS];       // per-row (mu, rstd) of g_h
__device__ float  g_qkv[MROWS*NQKV];    // qkv projection
__device__ float  g_Wp [NLAY*CH*NQKV];  // gamma-scaled qkv weights
__device__ float  g_G  [NLAY*NQKV];     // sum_k gamma_k W[k][n]
__device__ float  g_P2 [NLAY*NQKV];     // sum_k beta_k W[k][n] + qkv_bias[n]

// ---------------- packed f32x2 helpers --------------------------------------
__device__ __forceinline__ ull pk2(float x, float y) {
    ull r;
    asm("mov.b64 %0, {%1, %2};"
        : "=l"(r) : "r"(__float_as_uint(x)), "r"(__float_as_uint(y)));
    return r;
}
__device__ __forceinline__ ull fma2(ull a, ull b, ull c) {
    ull d;
    asm("fma.rn.f32x2 %0, %1, %2, %3;" : "=l"(d) : "l"(a), "l"(b), "l"(c));
    return d;
}
__device__ __forceinline__ void upk2(ull v, float& x, float& y) {
    unsigned int lo, hi;
    asm("mov.b64 {%0, %1}, %2;" : "=r"(lo), "=r"(hi) : "l"(v));
    x = __uint_as_float(lo);
    y = __uint_as_float(hi);
}
__device__ __forceinline__ float ex2(float x) {
    float r;
    asm("ex2.approx.f32 %0, %1;" : "=f"(r) : "f"(x));
    return r;
}

// ---------------- weight prep: W' = gamma*W; G, P2 per (layer, n) ------------
// grid (NQKV, NLAY), block 128 (= k). Deterministic in-block reduction.
__global__ void __launch_bounds__(128) prep_kernel(const float* __restrict__ qkv_w,
                                                   const float* __restrict__ qkv_b,
                                                   const float* __restrict__ ln_g,
                                                   const float* __restrict__ ln_b) {
    int n = blockIdx.x;
    int l = blockIdx.y;
    int k = threadIdx.x;
    int lane = k & 31, wid = k >> 5;

    float w = qkv_w[((size_t)l * CH + k) * NQKV + n];
    float g = ln_g[l * CH + k];
    float b = ln_b[l * CH + k];
    float gw = g * w;
    float bw = b * w;
    g_Wp[((size_t)l * CH + k) * NQKV + n] = gw;

    __shared__ float sG[4], sB[4];
#pragma unroll
    for (int o = 16; o; o >>= 1) {
        gw += __shfl_xor_sync(0xffffffffu, gw, o);
        bw += __shfl_xor_sync(0xffffffffu, bw, o);
    }
    if (lane == 0) { sG[wid] = gw; sB[wid] = bw; }
    __syncthreads();
    if (k == 0) {
        g_G [l * NQKV + n] = sG[0] + sG[1] + sG[2] + sG[3];
        g_P2[l * NQKV + n] = sB[0] + sB[1] + sB[2] + sB[3] + qkv_b[l * NQKV + n];
    }
}

// ---------------- input projection + LN stats --------------------------------
__global__ void __launch_bounds__(256) inproj_kernel(const float* __restrict__ x,
                                                     const float* __restrict__ in_w,
                                                     const float* __restrict__ in_b) {
    int row  = blockIdx.x * 8 + (threadIdx.x >> 5);
    int lane = threadIdx.x & 31;
    float x0 = __ldg(&x[row * 2]);
    float x1 = __ldg(&x[row * 2 + 1]);
    float s = 0.f, ss = 0.f;
    float* hr = g_h + (size_t)row * CH;
#pragma unroll
    for (int j = 0; j < 4; j++) {
        int c = lane + 32 * j;
        float h = fmaf(x0, in_w[c], fmaf(x1, in_w[CH + c], in_b[c]));
        hr[c] = h;
        s += h;
        ss = fmaf(h, h, ss);
    }
#pragma unroll
    for (int o = 16; o; o >>= 1) {
        s  += __shfl_xor_sync(0xffffffffu, s, o);
        ss += __shfl_xor_sync(0xffffffffu, ss, o);
    }
    if (lane == 0) {
        float mu  = s * (1.0f / CH);
        float var = fmaf(-mu, mu, ss * (1.0f / CH));
        g_stats[row] = make_float2(mu, rsqrtf(var + EPSLN));
    }
}

// ---------------- QKV GEMM: plain h @ W', LN applied in epilogue -------------
// 64x64 tile, double-buffered, As padded [16][68] (2-way staging conflicts,
// 16B-aligned rows for inner LDS.128). Epilogue: c1*acc + c0*G + P2.
__global__ void __launch_bounds__(256) qkv_gemm(int l) {
    __shared__ __align__(16) float As[2][16][68];
    __shared__ __align__(16) float Bs[2][16][64];

    int tid = threadIdx.x;
    int tx  = tid & 15;
    int ty  = tid >> 4;

    ull acc[4][2];
#pragma unroll
    for (int m = 0; m < 4; m++) { acc[m][0] = 0ull; acc[m][1] = 0ull; }

    int ar = tid >> 2;             // A staging row 0..63
    int ac = (tid & 3) << 2;       // A staging k offset 0,4,8,12
    int br = tid >> 4;             // B staging k row 0..15
    int bc = (tid & 15) << 2;      // B staging col

    size_t mBase = (size_t)blockIdx.y * 64;
    const float* Aload = g_h + (mBase + ar) * CH + ac;
    const float* Bload = g_Wp + (size_t)l * CH * NQKV
                              + (size_t)br * NQKV + blockIdx.x * 64 + bc;

    // prologue: fetch + stage chunk 0 (pure copies)
    float4 pa = *(const float4*)(Aload);
    float4 pb = *(const float4*)(Bload);
    As[0][ac + 0][ar] = pa.x;
    As[0][ac + 1][ar] = pa.y;
    As[0][ac + 2][ar] = pa.z;
    As[0][ac + 3][ar] = pa.w;
    *(float4*)&Bs[0][br][bc] = pb;
    __syncthreads();

#pragma unroll
    for (int i = 0; i < 8; i++) {
        int buf = i & 1;
        if (i < 7) {               // prefetch chunk i+1 into regs
            pa = *(const float4*)(Aload + (i + 1) * 16);
            pb = *(const float4*)(Bload + (size_t)(i + 1) * 16 * NQKV);
        }
#pragma unroll
        for (int k = 0; k < 16; k++) {
            float4 a4 = *(const float4*)&As[buf][k][ty << 2];   // LDS.128 broadcast
            float4 b4 = *(const float4*)&Bs[buf][k][tx << 2];
            ull b01 = pk2(b4.x, b4.y);
            ull b23 = pk2(b4.z, b4.w);
            ull a0 = pk2(a4.x, a4.x);
            ull a1 = pk2(a4.y, a4.y);
            ull a2 = pk2(a4.z, a4.z);
            ull a3 = pk2(a4.w, a4.w);
            acc[0][0] = fma2(a0, b01, acc[0][0]);
            acc[0][1] = fma2(a0, b23, acc[0][1]);
            acc[1][0] = fma2(a1, b01, acc[1][0]);
            acc[1][1] = fma2(a1, b23, acc[1][1]);
            acc[2][0] = fma2(a2, b01, acc[2][0]);
            acc[2][1] = fma2(a2, b23, acc[2][1]);
            acc[3][0] = fma2(a3, b01, acc[3][0]);
            acc[3][1] = fma2(a3, b23, acc[3][1]);
        }
        if (i < 7) {               // stage chunk i+1 into the other buffer
            int nb = buf ^ 1;
            As[nb][ac + 0][ar] = pa.x;
            As[nb][ac + 1][ar] = pa.y;
            As[nb][ac + 2][ar] = pa.z;
            As[nb][ac + 3][ar] = pa.w;
            *(float4*)&Bs[nb][br][bc] = pb;
            __syncthreads();
        }
    }

    int col = blockIdx.x * 64 + (tx << 2);
    float4 G4 = *(const float4*)(g_G  + l * NQKV + col);
    float4 P4 = *(const float4*)(g_P2 + l * NQKV + col);
#pragma unroll
    for (int m = 0; m < 4; m++) {
        size_t row = mBase + (ty << 2) + m;
        float2 st = g_stats[row];
        float c1 = st.y;           // rstd
        float c0 = -st.x * st.y;   // -mu*rstd
        float r0, r1, r2, r3;
        upk2(acc[m][0], r0, r1);
        upk2(acc[m][1], r2, r3);
        r0 = fmaf(c1, r0, fmaf(c0, G4.x, P4.x));
        r1 = fmaf(c1, r1, fmaf(c0, G4.y, P4.y));
        r2 = fmaf(c1, r2, fmaf(c0, G4.z, P4.z));
        r3 = fmaf(c1, r3, fmaf(c0, G4.w, P4.w));
        *(float4*)(g_qkv + row * NQKV + col) = make_float4(r0, r1, r2, r3);
    }
}

// ---------------- fused attention + FFN + residual + LN stats (R13/R14 WIN) --
#define QT 9
#define KT 27
__global__ void __launch_bounds__(128, 8) attn_ffn_kernel(const float* __restrict__ W,
                                                          const float* __restrict__ bias) {
    int b  = blockIdx.y;
    int q0 = blockIdx.x * QT;
    int c  = threadIdx.x;

    __shared__ float ks[KT][CH];
    __shared__ float vs[KT][CH];

    const float* base = g_qkv + (size_t)b * SEQ * NQKV;
    const float LOG2E = 1.4426950408889634f;

    float qv[QT], num[QT], den[QT];
#pragma unroll
    for (int i = 0; i < QT; i++) {
        qv[i]  = base[(size_t)(q0 + i) * NQKV + c] * LOG2E;
        num[i] = 0.f;
        den[i] = 0.f;
    }

#pragma unroll 1
    for (int kc = 0; kc < SEQ; kc += KT) {
        __syncthreads();
#pragma unroll
        for (int r = 0; r < KT; r++) {
            ks[r][c] = base[(size_t)(kc + r) * NQKV + CH     + c];
            vs[r][c] = base[(size_t)(kc + r) * NQKV + 2 * CH + c];
        }
        __syncthreads();
#pragma unroll 3
        for (int r = 0; r < KT; r++) {
            float kk = ks[r][c];
            float vv = vs[r][c];
#pragma unroll
            for (int i = 0; i < QT; i++) {
                float e = ex2(qv[i] * kk);
                num[i] = fmaf(e, vv, num[i]);
                den[i] += e;
            }
        }
    }

    // ---- stage att rows in smem (reuse ks; all warps done reading it) ------
    __syncthreads();
    float (*att_s)[CH] = ks;
#pragma unroll
    for (int i = 0; i < QT; i++) att_s[i][c] = __fdividef(num[i], den[i]);
    __syncthreads();

    // ---- FFN: y[i] = sum_k att[i][k] * W[k][c]  (idle FMA pipe) ------------
    float y[QT];
#pragma unroll
    for (int i = 0; i < QT; i++) y[i] = 0.f;
#pragma unroll 2
    for (int k = 0; k < CH; k += 4) {
        float w0 = W[(size_t)(k + 0) * CH + c];
        float w1 = W[(size_t)(k + 1) * CH + c];
        float w2 = W[(size_t)(k + 2) * CH + c];
        float w3 = W[(size_t)(k + 3) * CH + c];
#pragma unroll
        for (int i = 0; i < QT; i++) {
            float4 a = *(const float4*)&att_s[i][k];   // LDS.128 broadcast
            y[i] = fmaf(a.x, w0, y[i]);
            y[i] = fmaf(a.y, w1, y[i]);
            y[i] = fmaf(a.z, w2, y[i]);
            y[i] = fmaf(a.w, w3, y[i]);
        }
    }

    // ---- bias + relu + residual + write h; collect per-row stats -----------
    float bb = bias[c];
    size_t rowBase = (size_t)b * SEQ + q0;
    int wid  = c >> 5;
    int lane = c & 31;
    float* rs  = (float*)vs;           // [4][QT] partial sums (vs is dead)
    float* rss = rs + 4 * QT;          // [4][QT] partial sumsq

    float hn[QT];
#pragma unroll
    for (int i = 0; i < QT; i++) {
        float v = fmaxf(y[i] + bb, 0.f);
        float* hp = g_h + (rowBase + i) * CH + c;
        float h = *hp + v;
        *hp = h;
        hn[i] = h;
    }
#pragma unroll
    for (int i = 0; i < QT; i++) {
        float s  = hn[i];
        float ss = hn[i] * hn[i];
#pragma unroll
        for (int o = 16; o; o >>= 1) {
            s  += __shfl_xor_sync(0xffffffffu, s, o);
            ss += __shfl_xor_sync(0xffffffffu, ss, o);
        }
        if (lane == 0) { rs[wid * QT + i] = s; rss[wid * QT + i] = ss; }
    }
    __syncthreads();
    if (c < QT) {
        float s  = rs[c]  + rs[QT + c]  + rs[2 * QT + c]  + rs[3 * QT + c];
        float ss = rss[c] + rss[QT + c] + rss[2 * QT + c] + rss[3 * QT + c];
        float mu  = s * (1.0f / CH);
        float var = fmaf(-mu, mu, ss * (1.0f / CH));
        g_stats[rowBase + c] = make_float2(mu, rsqrtf(var + EPSLN));
    }
}

// ---------------- final projection: out = h @ out_w + out_b ------------------
__global__ void __launch_bounds__(256) outproj_kernel(const float* __restrict__ ow,
                                                      const float* __restrict__ ob,
                                                      float* __restrict__ out) {
    int row  = blockIdx.x * 8 + (threadIdx.x >> 5);
    int lane = threadIdx.x & 31;
    const float* hr = g_h + (size_t)row * CH;
    float a0 = 0.f, a1 = 0.f, a2 = 0.f, a3 = 0.f;
#pragma unroll
    for (int j = 0; j < 4; j++) {
        int cidx = lane + 32 * j;
        float hv = hr[cidx];
        const float* w = ow + cidx * 4;
        a0 = fmaf(hv, w[0], a0);
        a1 = fmaf(hv, w[1], a1);
        a2 = fmaf(hv, w[2], a2);
        a3 = fmaf(hv, w[3], a3);
    }
#pragma unroll
    for (int o = 16; o; o >>= 1) {
        a0 += __shfl_xor_sync(0xffffffffu, a0, o);
        a1 += __shfl_xor_sync(0xffffffffu, a1, o);
        a2 += __shfl_xor_sync(0xffffffffu, a2, o);
        a3 += __shfl_xor_sync(0xffffffffu, a3, o);
    }
    if (lane == 0) {
        *(float4*)(out + (size_t)row * 4) =
            make_float4(a0 + ob[0], a1 + ob[1], a2 + ob[2], a3 + ob[3]);
    }
}

// ---------------- launch -----------------------------------------------------
extern "C" void kernel_launch(void* const* d_in, const int* in_sizes, int n_in,
                              void* d_out, int out_size) {
    const float* x      = (const float*)d_in[0];
    const float* in_w   = (const float*)d_in[1];
    const float* in_b   = (const float*)d_in[2];
    const float* ln_g   = (const float*)d_in[3];
    const float* ln_b   = (const float*)d_in[4];
    const float* qkv_w  = (const float*)d_in[5];
    const float* qkv_b  = (const float*)d_in[6];
    const float* full_w = (const float*)d_in[7];
    const float* full_b = (const float*)d_in[8];
    const float* out_w  = (const float*)d_in[9];
    const float* out_b  = (const float*)d_in[10];
    float* out = (float*)d_out;

    prep_kernel<<<dim3(NQKV, NLAY), 128>>>(qkv_w, qkv_b, ln_g, ln_b);
    inproj_kernel<<<MROWS / 8, 256>>>(x, in_w, in_b);

    for (int l = 0; l < 4; l++) {
        qkv_gemm<<<dim3(NQKV / 64, MROWS / 64), 256>>>(l);
        attn_ffn_kernel<<<dim3(SEQ / QT, TBS), 128>>>(
            full_w + (size_t)l * CH * CH, full_b + l * CH);
    }

    outproj_kernel<<<MROWS / 8, 256>>>(out_w, out_b, out);
}